// round 4
// baseline (speedup 1.0000x reference)
#include <cuda_runtime.h>
#include <math.h>

// GPT-2 small config (fixed by the problem)
#define NB   2
#define NT   1024
#define ND   768
#define NH   12
#define NL   12
#define NV   50257
#define NHD  64
#define NTOK (NB * NT)        // 2048 token rows
#define N3D  (3 * ND)         // 2304
#define N4D  (4 * ND)         // 3072

// ---------------------------------------------------------------------------
// Scratch (device globals; allocation inside kernel_launch is forbidden)
// ---------------------------------------------------------------------------
__device__ float g_x  [NTOK * ND];          // residual stream
__device__ float g_h  [NTOK * ND];          // layernorm output
__device__ float g_qkv[NTOK * N3D];         // qkv projections
__device__ float g_ao [NTOK * ND];          // attention output (pre-proj)
__device__ float g_fc1[NTOK * N4D];         // MLP hidden
__device__ float g_att[(size_t)NB * NH * NT * NT];  // attention matrix (~100MB)

// ---------------------------------------------------------------------------
// Embedding: x = wte[idx] + pos
// ---------------------------------------------------------------------------
__global__ __launch_bounds__(256) void embed_k(const int* __restrict__ idx,
                                               const float* __restrict__ wte,
                                               const float* __restrict__ pos) {
    int i = blockIdx.x * 256 + threadIdx.x;
    if (i >= NTOK * ND) return;
    int tok = i / ND;
    int d   = i - tok * ND;
    int t   = tok & (NT - 1);
    g_x[i] = wte[(size_t)idx[tok] * ND + d] + pos[t * ND + d];
}

// ---------------------------------------------------------------------------
// LayerNorm: one block per token row (D=768, 256 threads x 3 elems)
// ---------------------------------------------------------------------------
__global__ __launch_bounds__(256) void ln_k(const float* __restrict__ in,
                                            const float* __restrict__ gamma,
                                            const float* __restrict__ beta,
                                            float* __restrict__ out) {
    int row = blockIdx.x;
    int tid = threadIdx.x;
    const float* x = in + (size_t)row * ND;
    float v0 = x[tid], v1 = x[tid + 256], v2 = x[tid + 512];

    __shared__ float red[256];
    __shared__ float s_mean, s_inv;

    red[tid] = v0 + v1 + v2;
    __syncthreads();
    for (int off = 128; off > 0; off >>= 1) {
        if (tid < off) red[tid] += red[tid + off];
        __syncthreads();
    }
    if (tid == 0) s_mean = red[0] * (1.0f / ND);
    __syncthreads();
    float m  = s_mean;
    float d0 = v0 - m, d1 = v1 - m, d2 = v2 - m;

    red[tid] = d0 * d0 + d1 * d1 + d2 * d2;
    __syncthreads();
    for (int off = 128; off > 0; off >>= 1) {
        if (tid < off) red[tid] += red[tid + off];
        __syncthreads();
    }
    if (tid == 0) s_inv = rsqrtf(red[0] * (1.0f / ND) + 1e-5f);
    __syncthreads();
    float inv = s_inv;

    float* o = out + (size_t)row * ND;
    o[tid]       = d0 * inv * gamma[tid]       + beta[tid];
    o[tid + 256] = d1 * inv * gamma[tid + 256] + beta[tid + 256];
    o[tid + 512] = d2 * inv * gamma[tid + 512] + beta[tid + 512];
}

// ---------------------------------------------------------------------------
// SGEMM: C[M,N] = A[M,K] @ W + epilogue
//   TB=false: W is [K,N] row-major.  TB=true: W is [N,K] row-major (B^T).
//   EPI: 0 = +bias, 1 = +bias+residual, 2 = +bias then exact GELU, 3 = none
// 128x128 block tile, BK=16, 256 threads, 8x8 per thread.
// ---------------------------------------------------------------------------
__device__ __forceinline__ float gelu_f(float v) {
    return 0.5f * v * (1.0f + erff(v * 0.70710678118654752f));
}

template <bool TB, int EPI>
__global__ __launch_bounds__(256) void sgemm_k(const float* __restrict__ A,
                                               const float* __restrict__ W,
                                               const float* __restrict__ bias,
                                               const float* __restrict__ res,
                                               float* __restrict__ C,
                                               int M, int N, int K) {
    __shared__ __align__(16) float As[16][132];  // padded: kills STS conflicts
    __shared__ __align__(16) float Bs[16][132];

    const int bm  = blockIdx.y * 128;
    const int bn  = blockIdx.x * 128;
    const int tid = threadIdx.x;
    const int tx  = tid & 15;   // 16 cols of threads
    const int ty  = tid >> 4;   // 16 rows of threads

    float acc[8][8];
#pragma unroll
    for (int i = 0; i < 8; i++)
#pragma unroll
        for (int j = 0; j < 8; j++) acc[i][j] = 0.0f;

    for (int k0 = 0; k0 < K; k0 += 16) {
        // A tile 128x16 (2048 elems / 256 threads = 8 each)
#pragma unroll
        for (int i = 0; i < 8; i++) {
            int idx = tid + i * 256;
            int m   = idx >> 4;
            int kk  = idx & 15;
            int gm  = bm + m;
            float v = (gm < M) ? A[(size_t)gm * K + k0 + kk] : 0.0f;
            As[kk][m] = v;
        }
        // B tile 16x128
#pragma unroll
        for (int i = 0; i < 8; i++) {
            int idx = tid + i * 256;
            int kk  = idx >> 7;
            int n   = idx & 127;
            int gn  = bn + n;
            float v = 0.0f;
            if (gn < N) {
                if (TB) v = W[(size_t)gn * K + (k0 + kk)];
                else    v = W[(size_t)(k0 + kk) * N + gn];
            }
            Bs[kk][n] = v;
        }
        __syncthreads();

#pragma unroll
        for (int kk = 0; kk < 16; kk++) {
            float a[8], b[8];
            *(float4*)&a[0] = *(const float4*)&As[kk][ty * 8];
            *(float4*)&a[4] = *(const float4*)&As[kk][ty * 8 + 4];
            *(float4*)&b[0] = *(const float4*)&Bs[kk][tx * 8];
            *(float4*)&b[4] = *(const float4*)&Bs[kk][tx * 8 + 4];
#pragma unroll
            for (int i = 0; i < 8; i++)
#pragma unroll
                for (int j = 0; j < 8; j++)
                    acc[i][j] = fmaf(a[i], b[j], acc[i][j]);
        }
        __syncthreads();
    }

#pragma unroll
    for (int i = 0; i < 8; i++) {
        int gm = bm + ty * 8 + i;
        if (gm >= M) continue;
#pragma unroll
        for (int j = 0; j < 8; j++) {
            int gn = bn + tx * 8 + j;
            if (gn >= N) continue;
            float v = acc[i][j];
            if (EPI != 3) v += bias[gn];
            if (EPI == 1) v += res[(size_t)gm * N + gn];
            if (EPI == 2) v = gelu_f(v);
            C[(size_t)gm * N + gn] = v;
        }
    }
}

// ---------------------------------------------------------------------------
// Attention scores: S[bh, q, k] = (Q . K) * 1/8   (64x64 tiles over 64 dims)
// Tiles fully above the diagonal are skipped; masking done in softmax.
// ---------------------------------------------------------------------------
__global__ __launch_bounds__(256) void attn_scores_k() {
    int bh = blockIdx.z;
    int b  = bh / NH;
    int h  = bh - b * NH;
    int q0 = blockIdx.y * 64;
    int k0 = blockIdx.x * 64;
    if (k0 > q0) return;  // whole tile masked

    __shared__ float Qs[64][65];
    __shared__ float Ks[64][65];
    const float* base = g_qkv + (size_t)b * NT * N3D + h * NHD;

    for (int i = threadIdx.x; i < 64 * 64; i += 256) {
        int r = i >> 6, c = i & 63;
        Qs[r][c] = base[(size_t)(q0 + r) * N3D + c];         // Q slice
        Ks[r][c] = base[(size_t)(k0 + r) * N3D + ND + c];    // K slice
    }
    __syncthreads();

    int tx = threadIdx.x & 15, ty = threadIdx.x >> 4;
    float acc[4][4] = {};
#pragma unroll
    for (int d = 0; d < 64; d++) {
        float a[4], bb[4];
#pragma unroll
        for (int i = 0; i < 4; i++) a[i] = Qs[ty * 4 + i][d];
#pragma unroll
        for (int j = 0; j < 4; j++) bb[j] = Ks[tx * 4 + j][d];
#pragma unroll
        for (int i = 0; i < 4; i++)
#pragma unroll
            for (int j = 0; j < 4; j++)
                acc[i][j] = fmaf(a[i], bb[j], acc[i][j]);
    }

    float* S = g_att + ((size_t)bh * NT + q0) * NT + k0;
#pragma unroll
    for (int i = 0; i < 4; i++)
#pragma unroll
        for (int j = 0; j < 4; j++)
            S[(size_t)(ty * 4 + i) * NT + tx * 4 + j] = acc[i][j] * 0.125f;
}

// ---------------------------------------------------------------------------
// Causal softmax over each row; masked (k > q) entries written as exactly 0.
// ---------------------------------------------------------------------------
__global__ __launch_bounds__(256) void attn_softmax_k() {
    int row = blockIdx.x;            // bh*NT + q
    int tid = threadIdx.x;
    int q   = row & (NT - 1);
    float* S = g_att + (size_t)row * NT;

    __shared__ float red[256];

    float mx = -1e30f;
    for (int k = tid; k <= q; k += 256) mx = fmaxf(mx, S[k]);
    red[tid] = mx;
    __syncthreads();
    for (int off = 128; off > 0; off >>= 1) {
        if (tid < off) red[tid] = fmaxf(red[tid], red[tid + off]);
        __syncthreads();
    }
    mx = red[0];
    __syncthreads();

    float sum = 0.0f;
    for (int k = tid; k <= q; k += 256) {
        float e = __expf(S[k] - mx);
        S[k] = e;
        sum += e;
    }
    red[tid] = sum;
    __syncthreads();
    for (int off = 128; off > 0; off >>= 1) {
        if (tid < off) red[tid] += red[tid + off];
        __syncthreads();
    }
    float inv = 1.0f / red[0];

    for (int k = tid; k < NT; k += 256)
        S[k] = (k <= q) ? S[k] * inv : 0.0f;
}

// ---------------------------------------------------------------------------
// O = P @ V  (64 q-rows per block, full 64-dim output, k-loop stops at diag)
// ---------------------------------------------------------------------------
__global__ __launch_bounds__(256) void attn_av_k() {
    int bh = blockIdx.y;
    int b  = bh / NH;
    int h  = bh - b * NH;
    int q0 = blockIdx.x * 64;

    __shared__ float Ps[64][65];
    __shared__ float Vs[64][65];
    const float* P     = g_att + ((size_t)bh * NT + q0) * NT;
    const float* vbase = g_qkv + (size_t)b * NT * N3D + 2 * ND + h * NHD;

    int tx = threadIdx.x & 15, ty = threadIdx.x >> 4;
    float acc[4][4] = {};

    for (int k0 = 0; k0 <= q0; k0 += 64) {
        for (int i = threadIdx.x; i < 64 * 64; i += 256) {
            int r = i >> 6, c = i & 63;
            Ps[r][c] = P[(size_t)r * NT + k0 + c];
            Vs[r][c] = vbase[(size_t)(k0 + r) * N3D + c];
        }
        __syncthreads();
#pragma unroll
        for (int kk = 0; kk < 64; kk++) {
            float a[4], bb[4];
#pragma unroll
            for (int i = 0; i < 4; i++) a[i] = Ps[ty * 4 + i][kk];
#pragma unroll
            for (int j = 0; j < 4; j++) bb[j] = Vs[kk][tx * 4 + j];
#pragma unroll
            for (int i = 0; i < 4; i++)
#pragma unroll
                for (int j = 0; j < 4; j++)
                    acc[i][j] = fmaf(a[i], bb[j], acc[i][j]);
        }
        __syncthreads();
    }

    // scatter back to [B,T,D] layout
    float* o = g_ao + ((size_t)b * NT + q0) * ND + h * NHD;
#pragma unroll
    for (int i = 0; i < 4; i++)
#pragma unroll
        for (int j = 0; j < 4; j++)
            o[(size_t)(ty * 4 + i) * ND + tx * 4 + j] = acc[i][j];
}

// ---------------------------------------------------------------------------
// Host driver — graph-capturable: kernel launches only.
// ---------------------------------------------------------------------------
extern "C" void kernel_launch(void* const* d_in, const int* in_sizes, int n_in,
                              void* d_out, int out_size) {
    const int*   idx   = (const int*)  d_in[0];
    const float* wte   = (const float*)d_in[1];
    const float* pos   = (const float*)d_in[2];
    const float* ln1g  = (const float*)d_in[3];
    const float* ln1b  = (const float*)d_in[4];
    const float* qkvw  = (const float*)d_in[5];
    const float* qkvb  = (const float*)d_in[6];
    const float* projw = (const float*)d_in[7];
    const float* projb = (const float*)d_in[8];
    const float* ln2g  = (const float*)d_in[9];
    const float* ln2b  = (const float*)d_in[10];
    const float* fc1w  = (const float*)d_in[11];
    const float* fc1b  = (const float*)d_in[12];
    const float* fc2w  = (const float*)d_in[13];
    const float* fc2b  = (const float*)d_in[14];
    const float* lnfg  = (const float*)d_in[15];
    const float* lnfb  = (const float*)d_in[16];

    float *px, *ph, *pao, *pfc1;
    cudaGetSymbolAddress((void**)&px,   g_x);
    cudaGetSymbolAddress((void**)&ph,   g_h);
    cudaGetSymbolAddress((void**)&pao,  g_ao);
    cudaGetSymbolAddress((void**)&pfc1, g_fc1);
    float* pqkv;
    cudaGetSymbolAddress((void**)&pqkv, g_qkv);

    embed_k<<<(NTOK * ND + 255) / 256, 256>>>(idx, wte, pos);

    for (int l = 0; l < NL; l++) {
        // --- attention half ---
        ln_k<<<NTOK, 256>>>(px, ln1g + (size_t)l * ND, ln1b + (size_t)l * ND, ph);

        dim3 gq(N3D / 128, NTOK / 128);
        sgemm_k<false, 0><<<gq, 256>>>(ph, qkvw + (size_t)l * ND * N3D,
                                       qkvb + (size_t)l * N3D, nullptr,
                                       pqkv, NTOK, N3D, ND);

        dim3 gs(NT / 64, NT / 64, NB * NH);
        attn_scores_k<<<gs, 256>>>();
        attn_softmax_k<<<NB * NH * NT, 256>>>();
        dim3 ga(NT / 64, NB * NH);
        attn_av_k<<<ga, 256>>>();

        dim3 gp(ND / 128, NTOK / 128);
        sgemm_k<false, 1><<<gp, 256>>>(pao, projw + (size_t)l * ND * ND,
                                       projb + (size_t)l * ND, px,
                                       px, NTOK, ND, ND);

        // --- MLP half ---
        ln_k<<<NTOK, 256>>>(px, ln2g + (size_t)l * ND, ln2b + (size_t)l * ND, ph);

        dim3 g1(N4D / 128, NTOK / 128);
        sgemm_k<false, 2><<<g1, 256>>>(ph, fc1w + (size_t)l * ND * N4D,
                                       fc1b + (size_t)l * N4D, nullptr,
                                       pfc1, NTOK, N4D, ND);

        dim3 g2(ND / 128, NTOK / 128);
        sgemm_k<false, 1><<<g2, 256>>>(pfc1, fc2w + (size_t)l * N4D * ND,
                                       fc2b + (size_t)l * ND, px,
                                       px, NTOK, ND, N4D);
    }

    // final LN + tied head (W = wte is [V, D] row-major -> trans-B GEMM)
    ln_k<<<NTOK, 256>>>(px, lnfg, lnfb, ph);
    dim3 gh((NV + 127) / 128, NTOK / 128);
    sgemm_k<true, 3><<<gh, 256>>>(ph, wte, nullptr, nullptr,
                                  (float*)d_out, NTOK, NV, ND);
}